// round 14
// baseline (speedup 1.0000x reference)
#include <cuda_runtime.h>
#include <cuda_bf16.h>
#include <cstdint>

// ---------------------------------------------------------------------------
// Problem constants
// ---------------------------------------------------------------------------
static constexpr int TOK = 2048;
static constexpr int D   = 1024;
static constexpr int H3  = 3072;
static constexpr int NH  = 16;
static constexpr int NOFF = 44;

__device__ __constant__ int c_offs[NOFF] = {
    0,1,2,3,4,5,6,7,8,9,10,11,12,13,14,15,16,17,18,19,20,21,22,23,24,
    25,26,27,28,29,30,31,32,48,64,96,128,192,256,384,512,768,1024,1536};

// ---------------------------------------------------------------------------
// Scratch (allocation-free)
// ---------------------------------------------------------------------------
__device__ float g_qkv [TOK * H3];
__device__ float g_gate[TOK * D];
__device__ __nv_bfloat16 g_xh [TOK * D],      g_xl [TOK * D];
__device__ __nv_bfloat16 g_wfh[(H3 + D) * D], g_wfl[(H3 + D) * D];  // [Wqkv; Wgate]
__device__ __nv_bfloat16 g_woh[D * D],        g_wol[D * D];
__device__ __nv_bfloat16 g_a2h[TOK * D],      g_a2l[TOK * D];

// ---------------------------------------------------------------------------
// PTX helpers (portable sm_80+ PTX only)
// ---------------------------------------------------------------------------
__device__ __forceinline__ uint32_t smem_u32(const void* p) {
    uint32_t a;
    asm("{ .reg .u64 t; cvta.to.shared.u64 t, %1; cvt.u32.u64 %0, t; }"
        : "=r"(a) : "l"(p));
    return a;
}

#define CP_ASYNC16(dst, src) \
    asm volatile("cp.async.cg.shared.global [%0], [%1], 16;" :: "r"(dst), "l"(src))
#define CP_COMMIT() asm volatile("cp.async.commit_group;" ::: "memory")
#define CP_WAIT0()  asm volatile("cp.async.wait_group 0;"  ::: "memory")

#define LDMX4(r, addr) \
    asm volatile("ldmatrix.sync.aligned.m8n8.x4.shared.b16 {%0,%1,%2,%3}, [%4];" \
                 : "=r"((r)[0]), "=r"((r)[1]), "=r"((r)[2]), "=r"((r)[3]) : "r"(addr))

#define MMA16816(d, a, b0, b1) \
    asm volatile("mma.sync.aligned.m16n8k16.row.col.f32.bf16.bf16.f32 " \
                 "{%0,%1,%2,%3}, {%4,%5,%6,%7}, {%8,%9}, {%0,%1,%2,%3};" \
                 : "+f"((d)[0]), "+f"((d)[1]), "+f"((d)[2]), "+f"((d)[3]) \
                 : "r"((a)[0]), "r"((a)[1]), "r"((a)[2]), "r"((a)[3]), \
                   "r"(b0), "r"(b1))

// ---------------------------------------------------------------------------
// Fused fp32 -> bf16 hi/lo split; 4 consecutive float4s per thread.
// ---------------------------------------------------------------------------
static constexpr int X4  = TOK * D / 4;
static constexpr int WQ4 = H3 * D / 4;
static constexpr int WG4 = D * D / 4;
static constexpr int WO4 = D * D / 4;
static constexpr int TOT4 = X4 + WQ4 + WG4 + WO4;

__global__ __launch_bounds__(256) void split_all_kernel(
    const float4* __restrict__ x, const float4* __restrict__ wq,
    const float4* __restrict__ wg, const float4* __restrict__ wo,
    uint2* __restrict__ xh, uint2* __restrict__ xl,
    uint2* __restrict__ wfh, uint2* __restrict__ wfl,
    uint2* __restrict__ woh, uint2* __restrict__ wol)
{
    int i0 = (blockIdx.x * 256 + threadIdx.x) * 4;
    if (i0 >= TOT4) return;

    const float4* src; uint2 *dh, *dl; int j;
    if (i0 < X4)                 { src = x;  dh = xh;  dl = xl;  j = i0; }
    else if (i0 < X4 + WQ4)      { src = wq; dh = wfh; dl = wfl; j = i0 - X4; }
    else if (i0 < X4 + WQ4 + WG4){ src = wg; dh = wfh + WQ4; dl = wfl + WQ4; j = i0 - X4 - WQ4; }
    else                         { src = wo; dh = woh; dl = wol; j = i0 - X4 - WQ4 - WG4; }

    float4 a4[4];
#pragma unroll
    for (int t = 0; t < 4; t++) a4[t] = src[j + t];

#pragma unroll
    for (int t = 0; t < 4; t++) {
        float av[4] = {a4[t].x, a4[t].y, a4[t].z, a4[t].w};
        uint32_t hh[4], ll[4];
#pragma unroll
        for (int k = 0; k < 4; k++) {
            __nv_bfloat16 h = __float2bfloat16(av[k]);
            float r = av[k] - __bfloat162float(h);
            __nv_bfloat16 l = __float2bfloat16(r);
            hh[k] = (uint32_t)__bfloat16_as_ushort(h);
            ll[k] = (uint32_t)__bfloat16_as_ushort(l);
        }
        uint2 hv, lv;
        hv.x = hh[0] | (hh[1] << 16); hv.y = hh[2] | (hh[3] << 16);
        lv.x = ll[0] | (ll[1] << 16); lv.y = ll[2] | (ll[3] << 16);
        dh[j + t] = hv; dl[j + t] = lv;
    }
}

// ---------------------------------------------------------------------------
// BIG-TILE HMMA GEMM (fused qkv+gate): CTA 128x128, 8 warps (warp tile 64x32),
// K-chunk 32 (stage = 4 x 8KB = 32KB, 2 stages, 2 CTAs/SM).
// 64B-row swizzle: off(r,c) = r*64 + ((c ^ ((r>>1)&3))*16) — conflict-free
// for both cp.async stores and ldmatrix (4r + c^((r>>1)&3) distinct mod 8).
// Sequential fragment loading keeps live regs ~119.
// ---------------------------------------------------------------------------
__global__ __launch_bounds__(256, 2) void hmma_gemm128(
    const __nv_bfloat16* __restrict__ Ah, const __nv_bfloat16* __restrict__ Al,
    const __nv_bfloat16* __restrict__ Bh, const __nv_bfloat16* __restrict__ Bl,
    const float* __restrict__ bias0, const float* __restrict__ bias1,
    float* __restrict__ C0, float* __restrict__ C1,
    int N, int K, int NSPLIT)
{
    constexpr uint32_t T_SZ   = 128 * 64;         // 8KB per tile (128 rows x 64B)
    constexpr uint32_t OFF_AL = T_SZ;
    constexpr uint32_t OFF_BH = 2 * T_SZ;
    constexpr uint32_t OFF_BL = 3 * T_SZ;
    constexpr uint32_t STG    = 4 * T_SZ;         // 32KB per stage

    extern __shared__ char smraw[];
    uint32_t sb = (smem_u32(smraw) + 127u) & ~127u;

    const int tid  = threadIdx.x;
    const int lane = tid & 31;
    const int wid  = tid >> 5;
    const int wm   = wid & 1;       // 0..1 -> 64-row slab
    const int wn   = wid >> 1;      // 0..3 -> 32-col slab
    const int m0 = blockIdx.x * 128;   // m fastest -> B-tile L2 sharing
    const int n0 = blockIdx.y * 128;

    const int nchunk = K >> 5;      // 32

    float acc[4][4][4];
#pragma unroll
    for (int i = 0; i < 4; i++)
#pragma unroll
        for (int j = 0; j < 4; j++)
#pragma unroll
            for (int q = 0; q < 4; q++) acc[i][j][q] = 0.f;

    const int a_r0 = wm * 64 + ((lane >> 3) & 1) * 8 + (lane & 7);
    const int a_kc = (lane >> 4);
    const int b_r0 = wn * 32 + ((lane >> 4) & 1) * 8 + (lane & 7);
    const int b_kc = ((lane >> 3) & 1);

    // 64B-row swizzled offset (16B units: c 0..3)
    auto swoff = [](int r, int c) -> uint32_t {
        return (uint32_t)r * 64u + (uint32_t)(((c ^ ((r >> 1) & 3)) & 3) * 16);
    };

    // loader: 4 tiles x 512 chunks of 16B, 256 threads -> 8 cp.async/thread
    auto load_tile = [&](int i) {
        const int kb = i * 32;
        const uint32_t base = sb + (uint32_t)(i & 1) * STG;
#pragma unroll
        for (int t = 0; t < 2; t++) {
            int u = tid + t * 256;
            int r = u >> 2, c = u & 3;
            uint32_t sw = swoff(r, c);
            const size_t ga = (size_t)(m0 + r) * K + kb + c * 8;
            const size_t gb = (size_t)(n0 + r) * K + kb + c * 8;
            CP_ASYNC16(base + sw,          (const void*)(Ah + ga));
            CP_ASYNC16(base + OFF_AL + sw, (const void*)(Al + ga));
            CP_ASYNC16(base + OFF_BH + sw, (const void*)(Bh + gb));
            CP_ASYNC16(base + OFF_BL + sw, (const void*)(Bl + gb));
        }
    };

    load_tile(0);
    CP_COMMIT();

    for (int i = 0; i < nchunk; i++) {
        CP_WAIT0();
        __syncthreads();

        if (i + 1 < nchunk) load_tile(i + 1);
        CP_COMMIT();

        const uint32_t base = sb + (uint32_t)(i & 1) * STG;

#pragma unroll
        for (int ks = 0; ks < 2; ks++) {
            const int ac = ks * 2 + a_kc;
            const int bc = ks * 2 + b_kc;

            // ---- pass 1: Ah * Bh ----
            uint32_t afh[4][4], bfh[2][4];
#pragma unroll
            for (int mi = 0; mi < 4; mi++) {
                int r = a_r0 + mi * 16;
                LDMX4(afh[mi], base + swoff(r, ac));
            }
#pragma unroll
            for (int ng = 0; ng < 2; ng++) {
                int r = b_r0 + ng * 16;
                LDMX4(bfh[ng], base + OFF_BH + swoff(r, bc));
            }
#pragma unroll
            for (int mi = 0; mi < 4; mi++)
#pragma unroll
                for (int ni = 0; ni < 4; ni++)
                    MMA16816(acc[mi][ni], afh[mi],
                             bfh[ni >> 1][(ni & 1) * 2], bfh[ni >> 1][(ni & 1) * 2 + 1]);

            // ---- pass 2: Al * Bh ----
            {
                uint32_t afl[4][4];
#pragma unroll
                for (int mi = 0; mi < 4; mi++) {
                    int r = a_r0 + mi * 16;
                    LDMX4(afl[mi], base + OFF_AL + swoff(r, ac));
                }
#pragma unroll
                for (int mi = 0; mi < 4; mi++)
#pragma unroll
                    for (int ni = 0; ni < 4; ni++)
                        MMA16816(acc[mi][ni], afl[mi],
                                 bfh[ni >> 1][(ni & 1) * 2], bfh[ni >> 1][(ni & 1) * 2 + 1]);
            }

            // ---- pass 3: Ah * Bl ----
            {
                uint32_t bfl[2][4];
#pragma unroll
                for (int ng = 0; ng < 2; ng++) {
                    int r = b_r0 + ng * 16;
                    LDMX4(bfl[ng], base + OFF_BL + swoff(r, bc));
                }
#pragma unroll
                for (int mi = 0; mi < 4; mi++)
#pragma unroll
                    for (int ni = 0; ni < 4; ni++)
                        MMA16816(acc[mi][ni], afh[mi],
                                 bfl[ni >> 1][(ni & 1) * 2], bfl[ni >> 1][(ni & 1) * 2 + 1]);
            }
        }
    }

    const bool   gate_tile = (n0 >= NSPLIT);
    float*       Cb    = gate_tile ? C1 : C0;
    const float* bb    = gate_tile ? bias1 : bias0;
    const int    ncols = gate_tile ? (N - NSPLIT) : NSPLIT;
    const int    nb0   = n0 - (gate_tile ? NSPLIT : 0);

    const int mrow = lane >> 2;
    const int ncol = (lane & 3) * 2;

    float2 bias_r[4];
#pragma unroll
    for (int ni = 0; ni < 4; ni++) {
        const int n = nb0 + wn * 32 + ni * 8 + ncol;
        bias_r[ni] = *(const float2*)(bb + n);
    }

#pragma unroll
    for (int mi = 0; mi < 4; mi++) {
#pragma unroll
        for (int half = 0; half < 2; half++) {
            const int m = m0 + wm * 64 + mi * 16 + mrow + half * 8;
            float* crow = Cb + (size_t)m * ncols;
#pragma unroll
            for (int ni = 0; ni < 4; ni++) {
                const int n = nb0 + wn * 32 + ni * 8 + ncol;
                float v0 = acc[mi][ni][half * 2 + 0] + bias_r[ni].x;
                float v1 = acc[mi][ni][half * 2 + 1] + bias_r[ni].y;
                if (gate_tile) {
                    v0 = 1.f / (1.f + __expf(-v0));
                    v1 = 1.f / (1.f + __expf(-v1));
                }
                float2 o = {v0, v1};
                *(float2*)(crow + n) = o;
            }
        }
    }
}

// ---------------------------------------------------------------------------
// Small-tile HMMA GEMM (out proj, proven R13 config): CTA 64x128, 8 warps,
// warp tile 32x32, K-chunk 64, single sync per chunk, 2 CTAs/SM.
// ---------------------------------------------------------------------------
__global__ __launch_bounds__(256, 2) void hmma_gemm(
    const __nv_bfloat16* __restrict__ Ah, const __nv_bfloat16* __restrict__ Al,
    const __nv_bfloat16* __restrict__ Bh, const __nv_bfloat16* __restrict__ Bl,
    const float* __restrict__ bias0, float* __restrict__ C0,
    int N, int K)
{
    constexpr uint32_t A_SZ  = 64 * 128;
    constexpr uint32_t B_SZ  = 128 * 128;
    constexpr uint32_t OFF_AL = A_SZ;
    constexpr uint32_t OFF_BH = 2 * A_SZ;
    constexpr uint32_t OFF_BL = 2 * A_SZ + B_SZ;
    constexpr uint32_t STG    = 2 * A_SZ + 2 * B_SZ;  // 48KB

    extern __shared__ char smraw[];
    uint32_t sb = (smem_u32(smraw) + 127u) & ~127u;

    const int tid  = threadIdx.x;
    const int lane = tid & 31;
    const int wid  = tid >> 5;
    const int wm   = wid & 1;
    const int wn   = wid >> 1;
    const int m0 = blockIdx.x * 64;
    const int n0 = blockIdx.y * 128;

    const int nchunk = K >> 6;

    float acc[2][4][4];
#pragma unroll
    for (int i = 0; i < 2; i++)
#pragma unroll
        for (int j = 0; j < 4; j++)
#pragma unroll
            for (int q = 0; q < 4; q++) acc[i][j][q] = 0.f;

    const int a_r  = wm * 32 + ((lane >> 3) & 1) * 8 + (lane & 7);
    const int a_kc = (lane >> 4);
    const int b_r  = wn * 32 + ((lane >> 4) & 1) * 8 + (lane & 7);
    const int b_kc = ((lane >> 3) & 1);

    auto load_tile = [&](int i) {
        const int kb = i * 64;
        const uint32_t base = sb + (uint32_t)(i & 1) * STG;
#pragma unroll
        for (int t = 0; t < 2; t++) {
            int u = tid + t * 256;
            int row = u >> 3, c = u & 7;
            uint32_t sw = (uint32_t)row * 128u + (uint32_t)((c ^ (row & 7)) * 16);
            const size_t g = (size_t)(m0 + row) * K + kb + c * 8;
            CP_ASYNC16(base + sw,          (const void*)(Ah + g));
            CP_ASYNC16(base + OFF_AL + sw, (const void*)(Al + g));
        }
#pragma unroll
        for (int t = 0; t < 4; t++) {
            int u = tid + t * 256;
            int row = u >> 3, c = u & 7;
            uint32_t sw = (uint32_t)row * 128u + (uint32_t)((c ^ (row & 7)) * 16);
            const size_t g = (size_t)(n0 + row) * K + kb + c * 8;
            CP_ASYNC16(base + OFF_BH + sw, (const void*)(Bh + g));
            CP_ASYNC16(base + OFF_BL + sw, (const void*)(Bl + g));
        }
    };

    load_tile(0);
    CP_COMMIT();

    for (int i = 0; i < nchunk; i++) {
        CP_WAIT0();
        __syncthreads();

        if (i + 1 < nchunk) load_tile(i + 1);
        CP_COMMIT();

        const uint32_t base = sb + (uint32_t)(i & 1) * STG;

#pragma unroll
        for (int ks = 0; ks < 4; ks++) {
            uint32_t afh[2][4], afl[2][4], bfh[2][4], bfl[2][4];
#pragma unroll
            for (int mi = 0; mi < 2; mi++) {
                int r = a_r + mi * 16;
                uint32_t sw = (uint32_t)(((ks * 2 + a_kc) ^ (r & 7)) * 16);
                LDMX4(afh[mi], base + (uint32_t)r * 128u + sw);
                LDMX4(afl[mi], base + OFF_AL + (uint32_t)r * 128u + sw);
            }
#pragma unroll
            for (int ng = 0; ng < 2; ng++) {
                int r = b_r + ng * 16;
                uint32_t sw = (uint32_t)(((ks * 2 + b_kc) ^ (r & 7)) * 16);
                LDMX4(bfh[ng], base + OFF_BH + (uint32_t)r * 128u + sw);
                LDMX4(bfl[ng], base + OFF_BL + (uint32_t)r * 128u + sw);
            }

#pragma unroll
            for (int mi = 0; mi < 2; mi++)
#pragma unroll
                for (int ni = 0; ni < 4; ni++)
                    MMA16816(acc[mi][ni], afh[mi],
                             bfh[ni >> 1][(ni & 1) * 2], bfh[ni >> 1][(ni & 1) * 2 + 1]);
#pragma unroll
            for (int mi = 0; mi < 2; mi++)
#pragma unroll
                for (int ni = 0; ni < 4; ni++)
                    MMA16816(acc[mi][ni], afl[mi],
                             bfh[ni >> 1][(ni & 1) * 2], bfh[ni >> 1][(ni & 1) * 2 + 1]);
#pragma unroll
            for (int mi = 0; mi < 2; mi++)
#pragma unroll
                for (int ni = 0; ni < 4; ni++)
                    MMA16816(acc[mi][ni], afh[mi],
                             bfl[ni >> 1][(ni & 1) * 2], bfl[ni >> 1][(ni & 1) * 2 + 1]);
        }
    }

    const int mrow = lane >> 2;
    const int ncol = (lane & 3) * 2;

    float2 bias_r[4];
#pragma unroll
    for (int ni = 0; ni < 4; ni++) {
        const int n = n0 + wn * 32 + ni * 8 + ncol;
        bias_r[ni] = *(const float2*)(bias0 + n);
    }

#pragma unroll
    for (int mi = 0; mi < 2; mi++) {
#pragma unroll
        for (int half = 0; half < 2; half++) {
            const int m = m0 + wm * 32 + mi * 16 + mrow + half * 8;
            float* crow = C0 + (size_t)m * N;
#pragma unroll
            for (int ni = 0; ni < 4; ni++) {
                const int n = n0 + wn * 32 + ni * 8 + ncol;
                float2 o;
                o.x = acc[mi][ni][half * 2 + 0] + bias_r[ni].x;
                o.y = acc[mi][ni][half * 2 + 1] + bias_r[ni].y;
                *(float2*)(crow + n) = o;
            }
        }
    }
}

// ---------------------------------------------------------------------------
// Attention (R13 winner): CTA = 16 tokens x 1 head, 16 warps (512 thr),
// one warp per (token, head); dense rows staged in 24KB smem; both score
// sets via butterfly multi-reduce.
// ---------------------------------------------------------------------------
__global__ __launch_bounds__(512) void attn_kernel(
    const float* __restrict__ qkv, const float* __restrict__ gate,
    const float* __restrict__ pos_bias,
    __nv_bfloat16* __restrict__ a2h, __nv_bfloat16* __restrict__ a2l)
{
    __shared__ float sK[48 * 64];
    __shared__ float sV[48 * 64];

    const int t0   = blockIdx.x * 16;
    const int h    = blockIdx.y;
    const int tid  = threadIdx.x;
    const int lane = tid & 31;
    const int w    = tid >> 5;

    for (int idx = tid; idx < 48 * 16; idx += 512) {
        const int row = idx >> 4, c4 = idx & 15;
        const int gt = t0 - 32 + row;
        float4 kv = {0.f, 0.f, 0.f, 0.f}, vv = {0.f, 0.f, 0.f, 0.f};
        if (gt >= 0) {
            kv = *(const float4*)(qkv + (size_t)gt * H3 + D     + h * 64 + c4 * 4);
            vv = *(const float4*)(qkv + (size_t)gt * H3 + 2 * D + h * 64 + c4 * 4);
        }
        *(float4*)(sK + row * 64 + c4 * 4) = kv;
        *(float4*)(sV + row * 64 + c4 * 4) = vv;
    }
    __syncthreads();

    const int n    = t0 + w;
    const int base = w + 32;
    const float2 q2 = *(const float2*)(qkv + (size_t)n * H3 + h * 64 + lane * 2);
    const float NEG = -1e30f;
    const int offs_sp[12] = {32,48,64,96,128,192,256,384,512,768,1024,1536};

    float r[32];
#pragma unroll
    for (int o = 0; o < 32; o++) {
        const float2 k2 = *(const float2*)(sK + (base - o) * 64 + lane * 2);
        r[o] = q2.x * k2.x + q2.y * k2.y;
    }
#pragma unroll
    for (int m = 16, cnt = 32; m >= 1; m >>= 1, cnt >>= 1) {
        const int half = cnt >> 1;
        const bool hi = (lane & m) != 0;
#pragma unroll
        for (int i = 0; i < 16; i++) {
            if (i < half) {
                float a = r[i], b = r[i + half];
                float sel = hi ? a : b;
                float got = __shfl_xor_sync(0xffffffffu, sel, m);
                r[i] = hi ? (b + got) : (a + got);
            }
        }
    }
    float s0 = (n - lane >= 0) ? (r[0] * 0.125f + pos_bias[lane * NH + h]) : NEG;

    float q[32];
#pragma unroll
    for (int j = 0; j < 12; j++) {
        const int off = offs_sp[j];
        const int src = n - off;
        float p = 0.f;
        if (src >= 0) {
            float2 k2;
            if (off == 32) k2 = *(const float2*)(sK + (base - 32) * 64 + lane * 2);
            else           k2 = *(const float2*)(qkv + (size_t)src * H3 + D + h * 64 + lane * 2);
            p = q2.x * k2.x + q2.y * k2.y;
        }
        q[j] = p;
    }
#pragma unroll
    for (int j = 12; j < 32; j++) q[j] = 0.f;
#pragma unroll
    for (int m = 16, cnt = 32; m >= 1; m >>= 1, cnt >>= 1) {
        const int half = cnt >> 1;
        const bool hi = (lane & m) != 0;
#pragma unroll
        for (int i = 0; i < 16; i++) {
            if (i < half) {
                float a = q[i], b = q[i + half];
                float sel = hi ? a : b;
                float got = __shfl_xor_sync(0xffffffffu, sel, m);
                q[i] = hi ? (b + got) : (a + got);
            }
        }
    }
    float s1 = NEG;
    if (lane < 12) {
        const int off_l = c_offs[32 + lane];
        if (n - off_l >= 0)
            s1 = q[0] * 0.125f + pos_bias[(32 + lane) * NH + h];
    }

    float m = fmaxf(s0, s1);
    m = fmaxf(m, __shfl_xor_sync(0xffffffffu, m, 16));
    m = fmaxf(m, __shfl_xor_sync(0xffffffffu, m, 8));
    m = fmaxf(m, __shfl_xor_sync(0xffffffffu, m, 4));
    m = fmaxf(m, __shfl_xor_sync(0xffffffffu, m, 2));
    m = fmaxf(m, __shfl_xor_sync(0xffffffffu, m, 1));

    float e0 = (s0 > NEG) ? __expf(s0 - m) : 0.f;
    float e1 = (s1 > NEG) ? __expf(s1 - m) : 0.f;

    float sum = e0 + e1;
    sum += __shfl_xor_sync(0xffffffffu, sum, 16);
    sum += __shfl_xor_sync(0xffffffffu, sum, 8);
    sum += __shfl_xor_sync(0xffffffffu, sum, 4);
    sum += __shfl_xor_sync(0xffffffffu, sum, 2);
    sum += __shfl_xor_sync(0xffffffffu, sum, 1);
    const float inv = 1.f / sum;

    float acc0 = 0.f, acc1 = 0.f;
#pragma unroll
    for (int o = 0; o < 32; o++) {
        float al = __shfl_sync(0xffffffffu, e0, o);
        const float2 v2 = *(const float2*)(sV + (base - o) * 64 + lane * 2);
        acc0 = fmaf(al, v2.x, acc0);
        acc1 = fmaf(al, v2.y, acc1);
    }
#pragma unroll
    for (int j = 0; j < 12; j++) {
        const int off = offs_sp[j];
        const int src = n - off;
        if (src >= 0) {
            float al = __shfl_sync(0xffffffffu, e1, j);
            float2 v2;
            if (off == 32) v2 = *(const float2*)(sV + (base - 32) * 64 + lane * 2);
            else           v2 = *(const float2*)(qkv + (size_t)src * H3 + 2 * D + h * 64 + lane * 2);
            acc0 = fmaf(al, v2.x, acc0);
            acc1 = fmaf(al, v2.y, acc1);
        }
    }
    acc0 *= inv;
    acc1 *= inv;

    const int oi2 = n * D + h * 64 + lane * 2;
    const float2 g2 = *(const float2*)(gate + oi2);
    float v0 = acc0 * g2.x;
    float v1 = acc1 * g2.y;

    __nv_bfloat16 h0 = __float2bfloat16(v0);
    __nv_bfloat16 h1 = __float2bfloat16(v1);
    a2h[oi2]     = h0;
    a2h[oi2 + 1] = h1;
    a2l[oi2]     = __float2bfloat16(v0 - __bfloat162float(h0));
    a2l[oi2 + 1] = __float2bfloat16(v1 - __bfloat162float(h1));
}

// ---------------------------------------------------------------------------
// kernel_launch
// ---------------------------------------------------------------------------
extern "C" void kernel_launch(void* const* d_in, const int* in_sizes, int n_in,
                              void* d_out, int out_size)
{
    const float* x        = (const float*)d_in[0];
    const float* Wqkv     = (const float*)d_in[1];
    const float* bqkv     = (const float*)d_in[2];
    const float* Wout     = (const float*)d_in[3];
    const float* bout     = (const float*)d_in[4];
    const float* Wgate    = (const float*)d_in[5];
    const float* bgate    = (const float*)d_in[6];
    const float* pos_bias = (const float*)d_in[7];
    float* out = (float*)d_out;

    float *qkv, *gate;
    __nv_bfloat16 *xh, *xl, *wfh, *wfl, *woh, *wol, *a2h, *a2l;
    cudaGetSymbolAddress((void**)&qkv,  g_qkv);
    cudaGetSymbolAddress((void**)&gate, g_gate);
    cudaGetSymbolAddress((void**)&xh,  g_xh);  cudaGetSymbolAddress((void**)&xl,  g_xl);
    cudaGetSymbolAddress((void**)&wfh, g_wfh); cudaGetSymbolAddress((void**)&wfl, g_wfl);
    cudaGetSymbolAddress((void**)&woh, g_woh); cudaGetSymbolAddress((void**)&wol, g_wol);
    cudaGetSymbolAddress((void**)&a2h, g_a2h); cudaGetSymbolAddress((void**)&a2l, g_a2l);

    const int SMEM_G128 = 128 + 2 * 4 * 128 * 64;               // 128 + 65536
    const int SMEM_G64  = 128 + 2 * (2 * 64 * 128 + 2 * 128 * 128);  // 128 + 98304
    cudaFuncSetAttribute(hmma_gemm128, cudaFuncAttributeMaxDynamicSharedMemorySize, SMEM_G128);
    cudaFuncSetAttribute(hmma_gemm,    cudaFuncAttributeMaxDynamicSharedMemorySize, SMEM_G64);

    // 1) all fp32 -> bf16 hi/lo splits
    split_all_kernel<<<(TOT4 / 4 + 255) / 256, 256>>>(
        (const float4*)x, (const float4*)Wqkv, (const float4*)Wgate, (const float4*)Wout,
        (uint2*)xh, (uint2*)xl, (uint2*)wfh, (uint2*)wfl, (uint2*)woh, (uint2*)wol);

    // 2) fused qkv+gate GEMM: [2048, 4096] = x @ [Wqkv; Wgate]^T  (512 CTAs, 128x128)
    hmma_gemm128<<<dim3(TOK / 128, (H3 + D) / 128), 256, SMEM_G128>>>(
        xh, xl, wfh, wfl, bqkv, bgate, qkv, gate, H3 + D, D, H3);

    // 3) attention + gate -> split a2   (128 token groups x 16 heads)
    attn_kernel<<<dim3(TOK / 16, NH), 512>>>(qkv, gate, pos_bias, a2h, a2l);

    // 4) out = a2 @ Wout^T + bout   (256 CTAs, 64x128)
    hmma_gemm<<<dim3(TOK / 64, D / 128), 256, SMEM_G64>>>(
        a2h, a2l, woh, wol, bout, out, D, D);
}

// round 15
// speedup vs baseline: 1.0079x; 1.0079x over previous
#include <cuda_runtime.h>
#include <cuda_bf16.h>
#include <cstdint>

// ---------------------------------------------------------------------------
// Problem constants
// ---------------------------------------------------------------------------
static constexpr int TOK = 2048;
static constexpr int D   = 1024;
static constexpr int H3  = 3072;
static constexpr int NH  = 16;
static constexpr int NOFF = 44;

__device__ __constant__ int c_offs[NOFF] = {
    0,1,2,3,4,5,6,7,8,9,10,11,12,13,14,15,16,17,18,19,20,21,22,23,24,
    25,26,27,28,29,30,31,32,48,64,96,128,192,256,384,512,768,1024,1536};

// ---------------------------------------------------------------------------
// Scratch (allocation-free)
// ---------------------------------------------------------------------------
__device__ float g_qkv [TOK * H3];
__device__ float g_gate[TOK * D];
__device__ __nv_bfloat16 g_xh [TOK * D],      g_xl [TOK * D];
__device__ __nv_bfloat16 g_wfh[(H3 + D) * D], g_wfl[(H3 + D) * D];  // [Wqkv; Wgate]
__device__ __nv_bfloat16 g_woh[D * D],        g_wol[D * D];
__device__ __nv_bfloat16 g_a2h[TOK * D],      g_a2l[TOK * D];

// ---------------------------------------------------------------------------
// PTX helpers (portable sm_80+ PTX only)
// ---------------------------------------------------------------------------
__device__ __forceinline__ uint32_t smem_u32(const void* p) {
    uint32_t a;
    asm("{ .reg .u64 t; cvta.to.shared.u64 t, %1; cvt.u32.u64 %0, t; }"
        : "=r"(a) : "l"(p));
    return a;
}

#define CP_ASYNC16(dst, src) \
    asm volatile("cp.async.cg.shared.global [%0], [%1], 16;" :: "r"(dst), "l"(src))
#define CP_COMMIT() asm volatile("cp.async.commit_group;" ::: "memory")
#define CP_WAIT1()  asm volatile("cp.async.wait_group 1;"  ::: "memory")

#define LDMX4(r, addr) \
    asm volatile("ldmatrix.sync.aligned.m8n8.x4.shared.b16 {%0,%1,%2,%3}, [%4];" \
                 : "=r"((r)[0]), "=r"((r)[1]), "=r"((r)[2]), "=r"((r)[3]) : "r"(addr))

#define MMA16816(d, a, b0, b1) \
    asm volatile("mma.sync.aligned.m16n8k16.row.col.f32.bf16.bf16.f32 " \
                 "{%0,%1,%2,%3}, {%4,%5,%6,%7}, {%8,%9}, {%0,%1,%2,%3};" \
                 : "+f"((d)[0]), "+f"((d)[1]), "+f"((d)[2]), "+f"((d)[3]) \
                 : "r"((a)[0]), "r"((a)[1]), "r"((a)[2]), "r"((a)[3]), \
                   "r"(b0), "r"(b1))

// ---------------------------------------------------------------------------
// Fused fp32 -> bf16 hi/lo split; 4 consecutive float4s per thread.
// ---------------------------------------------------------------------------
static constexpr int X4  = TOK * D / 4;
static constexpr int WQ4 = H3 * D / 4;
static constexpr int WG4 = D * D / 4;
static constexpr int WO4 = D * D / 4;
static constexpr int TOT4 = X4 + WQ4 + WG4 + WO4;

__global__ __launch_bounds__(256) void split_all_kernel(
    const float4* __restrict__ x, const float4* __restrict__ wq,
    const float4* __restrict__ wg, const float4* __restrict__ wo,
    uint2* __restrict__ xh, uint2* __restrict__ xl,
    uint2* __restrict__ wfh, uint2* __restrict__ wfl,
    uint2* __restrict__ woh, uint2* __restrict__ wol)
{
    int i0 = (blockIdx.x * 256 + threadIdx.x) * 4;
    if (i0 >= TOT4) return;

    const float4* src; uint2 *dh, *dl; int j;
    if (i0 < X4)                 { src = x;  dh = xh;  dl = xl;  j = i0; }
    else if (i0 < X4 + WQ4)      { src = wq; dh = wfh; dl = wfl; j = i0 - X4; }
    else if (i0 < X4 + WQ4 + WG4){ src = wg; dh = wfh + WQ4; dl = wfl + WQ4; j = i0 - X4 - WQ4; }
    else                         { src = wo; dh = woh; dl = wol; j = i0 - X4 - WQ4 - WG4; }

    float4 a4[4];
#pragma unroll
    for (int t = 0; t < 4; t++) a4[t] = src[j + t];

#pragma unroll
    for (int t = 0; t < 4; t++) {
        float av[4] = {a4[t].x, a4[t].y, a4[t].z, a4[t].w};
        uint32_t hh[4], ll[4];
#pragma unroll
        for (int k = 0; k < 4; k++) {
            __nv_bfloat16 h = __float2bfloat16(av[k]);
            float r = av[k] - __bfloat162float(h);
            __nv_bfloat16 l = __float2bfloat16(r);
            hh[k] = (uint32_t)__bfloat16_as_ushort(h);
            ll[k] = (uint32_t)__bfloat16_as_ushort(l);
        }
        uint2 hv, lv;
        hv.x = hh[0] | (hh[1] << 16); hv.y = hh[2] | (hh[3] << 16);
        lv.x = ll[0] | (ll[1] << 16); lv.y = ll[2] | (ll[3] << 16);
        dh[j + t] = hv; dl[j + t] = lv;
    }
}

// ---------------------------------------------------------------------------
// HMMA GEMM, 3-stage pipeline: CTA 64x128, 8 warps (warp tile 32x32),
// K-chunk 32 -> stage = Ah(4K)+Al(4K)+Bh(8K)+Bl(8K) = 24KB, 3 stages = 72KB,
// 2 CTAs/SM. 64B-row swizzle (conflict-free, verified in R14).
// Loop: wait_group(1) [load(i) done, load(i+1) in flight]; one sync;
// issue load(i+2); compute(i). Dual epilogue, CTA-uniform.
// ---------------------------------------------------------------------------
__global__ __launch_bounds__(256, 2) void hmma_gemm(
    const __nv_bfloat16* __restrict__ Ah, const __nv_bfloat16* __restrict__ Al,
    const __nv_bfloat16* __restrict__ Bh, const __nv_bfloat16* __restrict__ Bl,
    const float* __restrict__ bias0, const float* __restrict__ bias1,
    float* __restrict__ C0, float* __restrict__ C1,
    int N, int K, int NSPLIT)
{
    constexpr uint32_t A_SZ  = 64 * 64;            // 4KB per A tile
    constexpr uint32_t B_SZ  = 128 * 64;           // 8KB per B tile
    constexpr uint32_t OFF_AL = A_SZ;              // 4KB
    constexpr uint32_t OFF_BH = 2 * A_SZ;          // 8KB
    constexpr uint32_t OFF_BL = 2 * A_SZ + B_SZ;   // 16KB
    constexpr uint32_t STG    = 2 * A_SZ + 2 * B_SZ;  // 24KB

    extern __shared__ char smraw[];
    uint32_t sb = (smem_u32(smraw) + 127u) & ~127u;

    const int tid  = threadIdx.x;
    const int lane = tid & 31;
    const int wid  = tid >> 5;
    const int wm   = wid & 1;
    const int wn   = wid >> 1;
    const int m0 = blockIdx.x * 64;     // m fastest -> B-tile L2 sharing
    const int n0 = blockIdx.y * 128;

    const int nchunk = K >> 5;          // Kc = 32

    float acc[2][4][4];
#pragma unroll
    for (int i = 0; i < 2; i++)
#pragma unroll
        for (int j = 0; j < 4; j++)
#pragma unroll
            for (int q = 0; q < 4; q++) acc[i][j][q] = 0.f;

    const int a_r  = wm * 32 + ((lane >> 3) & 1) * 8 + (lane & 7);
    const int a_kc = (lane >> 4);        // 0/1
    const int b_r  = wn * 32 + ((lane >> 4) & 1) * 8 + (lane & 7);
    const int b_kc = ((lane >> 3) & 1);  // 0/1

    // 64B-row swizzled offset; c in 16B units (0..3)
    auto swoff = [](int r, int c) -> uint32_t {
        return (uint32_t)r * 64u + (uint32_t)(((c ^ ((r >> 1) & 3)) & 3) * 16);
    };

    // loader: A 256 chunks each (1/thread), B 512 chunks each (2/thread)
    auto load_tile = [&](int i) {
        const int kb = i * 32;
        const uint32_t base = sb + (uint32_t)(i % 3) * STG;
        {
            int r = tid >> 2, c = tid & 3;
            uint32_t sw = swoff(r, c);
            const size_t g = (size_t)(m0 + r) * K + kb + c * 8;
            CP_ASYNC16(base + sw,          (const void*)(Ah + g));
            CP_ASYNC16(base + OFF_AL + sw, (const void*)(Al + g));
        }
#pragma unroll
        for (int t = 0; t < 2; t++) {
            int u = tid + t * 256;
            int r = u >> 2, c = u & 3;
            uint32_t sw = swoff(r, c);
            const size_t g = (size_t)(n0 + r) * K + kb + c * 8;
            CP_ASYNC16(base + OFF_BH + sw, (const void*)(Bh + g));
            CP_ASYNC16(base + OFF_BL + sw, (const void*)(Bl + g));
        }
    };

    load_tile(0); CP_COMMIT();
    load_tile(1); CP_COMMIT();

    for (int i = 0; i < nchunk; i++) {
        CP_WAIT1();            // load(i) complete; load(i+1) may be in flight
        __syncthreads();       // compute(i-1) finished -> stage (i+2)%3 reusable

        if (i + 2 < nchunk) load_tile(i + 2);
        CP_COMMIT();

        const uint32_t base = sb + (uint32_t)(i % 3) * STG;

#pragma unroll
        for (int ks = 0; ks < 2; ks++) {
            const int ac = ks * 2 + a_kc;
            const int bc = ks * 2 + b_kc;

            uint32_t afh[2][4], bfh[2][4];
#pragma unroll
            for (int mi = 0; mi < 2; mi++) {
                int r = a_r + mi * 16;
                LDMX4(afh[mi], base + swoff(r, ac));
            }
#pragma unroll
            for (int ng = 0; ng < 2; ng++) {
                int r = b_r + ng * 16;
                LDMX4(bfh[ng], base + OFF_BH + swoff(r, bc));
            }
            // pass 1: Ah * Bh
#pragma unroll
            for (int mi = 0; mi < 2; mi++)
#pragma unroll
                for (int ni = 0; ni < 4; ni++)
                    MMA16816(acc[mi][ni], afh[mi],
                             bfh[ni >> 1][(ni & 1) * 2], bfh[ni >> 1][(ni & 1) * 2 + 1]);
            // pass 2: Al * Bh
            {
                uint32_t afl[2][4];
#pragma unroll
                for (int mi = 0; mi < 2; mi++) {
                    int r = a_r + mi * 16;
                    LDMX4(afl[mi], base + OFF_AL + swoff(r, ac));
                }
#pragma unroll
                for (int mi = 0; mi < 2; mi++)
#pragma unroll
                    for (int ni = 0; ni < 4; ni++)
                        MMA16816(acc[mi][ni], afl[mi],
                                 bfh[ni >> 1][(ni & 1) * 2], bfh[ni >> 1][(ni & 1) * 2 + 1]);
            }
            // pass 3: Ah * Bl
            {
                uint32_t bfl[2][4];
#pragma unroll
                for (int ng = 0; ng < 2; ng++) {
                    int r = b_r + ng * 16;
                    LDMX4(bfl[ng], base + OFF_BL + swoff(r, bc));
                }
#pragma unroll
                for (int mi = 0; mi < 2; mi++)
#pragma unroll
                    for (int ni = 0; ni < 4; ni++)
                        MMA16816(acc[mi][ni], afh[mi],
                                 bfl[ni >> 1][(ni & 1) * 2], bfl[ni >> 1][(ni & 1) * 2 + 1]);
            }
        }
    }

    const bool   gate_tile = (n0 >= NSPLIT);
    float*       Cb    = gate_tile ? C1 : C0;
    const float* bb    = gate_tile ? bias1 : bias0;
    const int    ncols = gate_tile ? (N - NSPLIT) : NSPLIT;
    const int    nb0   = n0 - (gate_tile ? NSPLIT : 0);

    const int mrow = lane >> 2;
    const int ncol = (lane & 3) * 2;

    float2 bias_r[4];
#pragma unroll
    for (int ni = 0; ni < 4; ni++) {
        const int n = nb0 + wn * 32 + ni * 8 + ncol;
        bias_r[ni] = *(const float2*)(bb + n);
    }

#pragma unroll
    for (int mi = 0; mi < 2; mi++) {
#pragma unroll
        for (int half = 0; half < 2; half++) {
            const int m = m0 + wm * 32 + mi * 16 + mrow + half * 8;
            float* crow = Cb + (size_t)m * ncols;
#pragma unroll
            for (int ni = 0; ni < 4; ni++) {
                const int n = nb0 + wn * 32 + ni * 8 + ncol;
                float v0 = acc[mi][ni][half * 2 + 0] + bias_r[ni].x;
                float v1 = acc[mi][ni][half * 2 + 1] + bias_r[ni].y;
                if (gate_tile) {
                    v0 = 1.f / (1.f + __expf(-v0));
                    v1 = 1.f / (1.f + __expf(-v1));
                }
                float2 o = {v0, v1};
                *(float2*)(crow + n) = o;
            }
        }
    }
}

// ---------------------------------------------------------------------------
// Attention (R13 winner): CTA = 16 tokens x 1 head, 16 warps (512 thr),
// one warp per (token, head); dense rows staged in 24KB smem; both score
// sets via butterfly multi-reduce.
// ---------------------------------------------------------------------------
__global__ __launch_bounds__(512) void attn_kernel(
    const float* __restrict__ qkv, const float* __restrict__ gate,
    const float* __restrict__ pos_bias,
    __nv_bfloat16* __restrict__ a2h, __nv_bfloat16* __restrict__ a2l)
{
    __shared__ float sK[48 * 64];
    __shared__ float sV[48 * 64];

    const int t0   = blockIdx.x * 16;
    const int h    = blockIdx.y;
    const int tid  = threadIdx.x;
    const int lane = tid & 31;
    const int w    = tid >> 5;

    for (int idx = tid; idx < 48 * 16; idx += 512) {
        const int row = idx >> 4, c4 = idx & 15;
        const int gt = t0 - 32 + row;
        float4 kv = {0.f, 0.f, 0.f, 0.f}, vv = {0.f, 0.f, 0.f, 0.f};
        if (gt >= 0) {
            kv = *(const float4*)(qkv + (size_t)gt * H3 + D     + h * 64 + c4 * 4);
            vv = *(const float4*)(qkv + (size_t)gt * H3 + 2 * D + h * 64 + c4 * 4);
        }
        *(float4*)(sK + row * 64 + c4 * 4) = kv;
        *(float4*)(sV + row * 64 + c4 * 4) = vv;
    }
    __syncthreads();

    const int n    = t0 + w;
    const int base = w + 32;
    const float2 q2 = *(const float2*)(qkv + (size_t)n * H3 + h * 64 + lane * 2);
    const float NEG = -1e30f;
    const int offs_sp[12] = {32,48,64,96,128,192,256,384,512,768,1024,1536};

    float r[32];
#pragma unroll
    for (int o = 0; o < 32; o++) {
        const float2 k2 = *(const float2*)(sK + (base - o) * 64 + lane * 2);
        r[o] = q2.x * k2.x + q2.y * k2.y;
    }
#pragma unroll
    for (int m = 16, cnt = 32; m >= 1; m >>= 1, cnt >>= 1) {
        const int half = cnt >> 1;
        const bool hi = (lane & m) != 0;
#pragma unroll
        for (int i = 0; i < 16; i++) {
            if (i < half) {
                float a = r[i], b = r[i + half];
                float sel = hi ? a : b;
                float got = __shfl_xor_sync(0xffffffffu, sel, m);
                r[i] = hi ? (b + got) : (a + got);
            }
        }
    }
    float s0 = (n - lane >= 0) ? (r[0] * 0.125f + pos_bias[lane * NH + h]) : NEG;

    float q[32];
#pragma unroll
    for (int j = 0; j < 12; j++) {
        const int off = offs_sp[j];
        const int src = n - off;
        float p = 0.f;
        if (src >= 0) {
            float2 k2;
            if (off == 32) k2 = *(const float2*)(sK + (base - 32) * 64 + lane * 2);
            else           k2 = *(const float2*)(qkv + (size_t)src * H3 + D + h * 64 + lane * 2);
            p = q2.x * k2.x + q2.y * k2.y;
        }
        q[j] = p;
    }
#pragma unroll
    for (int j = 12; j < 32; j++) q[j] = 0.f;
#pragma unroll
    for (int m = 16, cnt = 32; m >= 1; m >>= 1, cnt >>= 1) {
        const int half = cnt >> 1;
        const bool hi = (lane & m) != 0;
#pragma unroll
        for (int i = 0; i < 16; i++) {
            if (i < half) {
                float a = q[i], b = q[i + half];
                float sel = hi ? a : b;
                float got = __shfl_xor_sync(0xffffffffu, sel, m);
                q[i] = hi ? (b + got) : (a + got);
            }
        }
    }
    float s1 = NEG;
    if (lane < 12) {
        const int off_l = c_offs[32 + lane];
        if (n - off_l >= 0)
            s1 = q[0] * 0.125f + pos_bias[(32 + lane) * NH + h];
    }

    float m = fmaxf(s0, s1);
    m = fmaxf(m, __shfl_xor_sync(0xffffffffu, m, 16));
    m = fmaxf(m, __shfl_xor_sync(0xffffffffu, m, 8));
    m = fmaxf(m, __shfl_xor_sync(0xffffffffu, m, 4));
    m = fmaxf(m, __shfl_xor_sync(0xffffffffu, m, 2));
    m = fmaxf(m, __shfl_xor_sync(0xffffffffu, m, 1));

    float e0 = (s0 > NEG) ? __expf(s0 - m) : 0.f;
    float e1 = (s1 > NEG) ? __expf(s1 - m) : 0.f;

    float sum = e0 + e1;
    sum += __shfl_xor_sync(0xffffffffu, sum, 16);
    sum += __shfl_xor_sync(0xffffffffu, sum, 8);
    sum += __shfl_xor_sync(0xffffffffu, sum, 4);
    sum += __shfl_xor_sync(0xffffffffu, sum, 2);
    sum += __shfl_xor_sync(0xffffffffu, sum, 1);
    const float inv = 1.f / sum;

    float acc0 = 0.f, acc1 = 0.f;
#pragma unroll
    for (int o = 0; o < 32; o++) {
        float al = __shfl_sync(0xffffffffu, e0, o);
        const float2 v2 = *(const float2*)(sV + (base - o) * 64 + lane * 2);
        acc0 = fmaf(al, v2.x, acc0);
        acc1 = fmaf(al, v2.y, acc1);
    }
#pragma unroll
    for (int j = 0; j < 12; j++) {
        const int off = offs_sp[j];
        const int src = n - off;
        if (src >= 0) {
            float al = __shfl_sync(0xffffffffu, e1, j);
            float2 v2;
            if (off == 32) v2 = *(const float2*)(sV + (base - 32) * 64 + lane * 2);
            else           v2 = *(const float2*)(qkv + (size_t)src * H3 + 2 * D + h * 64 + lane * 2);
            acc0 = fmaf(al, v2.x, acc0);
            acc1 = fmaf(al, v2.y, acc1);
        }
    }
    acc0 *= inv;
    acc1 *= inv;

    const int oi2 = n * D + h * 64 + lane * 2;
    const float2 g2 = *(const float2*)(gate + oi2);
    float v0 = acc0 * g2.x;
    float v1 = acc1 * g2.y;

    __nv_bfloat16 h0 = __float2bfloat16(v0);
    __nv_bfloat16 h1 = __float2bfloat16(v1);
    a2h[oi2]     = h0;
    a2h[oi2 + 1] = h1;
    a2l[oi2]     = __float2bfloat16(v0 - __bfloat162float(h0));
    a2l[oi2 + 1] = __float2bfloat16(v1 - __bfloat162float(h1));
}

// ---------------------------------------------------------------------------
// kernel_launch
// ---------------------------------------------------------------------------
extern "C" void kernel_launch(void* const* d_in, const int* in_sizes, int n_in,
                              void* d_out, int out_size)
{
    const float* x        = (const float*)d_in[0];
    const float* Wqkv     = (const float*)d_in[1];
    const float* bqkv     = (const float*)d_in[2];
    const float* Wout     = (const float*)d_in[3];
    const float* bout     = (const float*)d_in[4];
    const float* Wgate    = (const float*)d_in[5];
    const float* bgate    = (const float*)d_in[6];
    const float* pos_bias = (const float*)d_in[7];
    float* out = (float*)d_out;

    float *qkv, *gate;
    __nv_bfloat16 *xh, *xl, *wfh, *wfl, *woh, *wol, *a2h, *a2l;
    cudaGetSymbolAddress((void**)&qkv,  g_qkv);
    cudaGetSymbolAddress((void**)&gate, g_gate);
    cudaGetSymbolAddress((void**)&xh,  g_xh);  cudaGetSymbolAddress((void**)&xl,  g_xl);
    cudaGetSymbolAddress((void**)&wfh, g_wfh); cudaGetSymbolAddress((void**)&wfl, g_wfl);
    cudaGetSymbolAddress((void**)&woh, g_woh); cudaGetSymbolAddress((void**)&wol, g_wol);
    cudaGetSymbolAddress((void**)&a2h, g_a2h); cudaGetSymbolAddress((void**)&a2l, g_a2l);

    const int SMEM_GEMM = 128 + 3 * (2 * 64 * 64 + 2 * 128 * 64);   // 128 + 73728
    cudaFuncSetAttribute(hmma_gemm, cudaFuncAttributeMaxDynamicSharedMemorySize, SMEM_GEMM);

    // 1) all fp32 -> bf16 hi/lo splits
    split_all_kernel<<<(TOT4 / 4 + 255) / 256, 256>>>(
        (const float4*)x, (const float4*)Wqkv, (const float4*)Wgate, (const float4*)Wout,
        (uint2*)xh, (uint2*)xl, (uint2*)wfh, (uint2*)wfl, (uint2*)woh, (uint2*)wol);

    // 2) fused qkv+gate GEMM: [2048, 4096] = x @ [Wqkv; Wgate]^T   (1024 CTAs)
    hmma_gemm<<<dim3(TOK / 64, (H3 + D) / 128), 256, SMEM_GEMM>>>(
        xh, xl, wfh, wfl, bqkv, bgate, qkv, gate, H3 + D, D, H3);

    // 3) attention + gate -> split a2   (128 token groups x 16 heads)
    attn_kernel<<<dim3(TOK / 16, NH), 512>>>(qkv, gate, pos_bias, a2h, a2l);

    // 4) out = a2 @ Wout^T + bout   (256 CTAs)
    hmma_gemm<<<dim3(TOK / 64, D / 128), 256, SMEM_GEMM>>>(
        a2h, a2l, woh, wol, bout, bout, out, nullptr, D, D, D);
}

// round 16
// speedup vs baseline: 1.0363x; 1.0282x over previous
#include <cuda_runtime.h>
#include <cuda_bf16.h>
#include <cstdint>

// ---------------------------------------------------------------------------
// Problem constants
// ---------------------------------------------------------------------------
static constexpr int TOK = 2048;
static constexpr int D   = 1024;
static constexpr int H3  = 3072;
static constexpr int NH  = 16;
static constexpr int NOFF = 44;

__device__ __constant__ int c_offs[NOFF] = {
    0,1,2,3,4,5,6,7,8,9,10,11,12,13,14,15,16,17,18,19,20,21,22,23,24,
    25,26,27,28,29,30,31,32,48,64,96,128,192,256,384,512,768,1024,1536};

// ---------------------------------------------------------------------------
// Scratch (allocation-free)
// ---------------------------------------------------------------------------
__device__ float g_qkv [TOK * H3];
__device__ float g_gate[TOK * D];
__device__ __nv_bfloat16 g_xh [TOK * D],      g_xl [TOK * D];
__device__ __nv_bfloat16 g_wfh[(H3 + D) * D], g_wfl[(H3 + D) * D];  // [Wqkv; Wgate]
__device__ __nv_bfloat16 g_woh[D * D],        g_wol[D * D];
__device__ __nv_bfloat16 g_a2h[TOK * D],      g_a2l[TOK * D];

// ---------------------------------------------------------------------------
// PTX helpers (portable sm_80+ PTX only)
// ---------------------------------------------------------------------------
__device__ __forceinline__ uint32_t smem_u32(const void* p) {
    uint32_t a;
    asm("{ .reg .u64 t; cvta.to.shared.u64 t, %1; cvt.u32.u64 %0, t; }"
        : "=r"(a) : "l"(p));
    return a;
}

#define CP_ASYNC16(dst, src) \
    asm volatile("cp.async.cg.shared.global [%0], [%1], 16;" :: "r"(dst), "l"(src))
#define CP_ASYNC16_Z(dst, src, nbytes) \
    asm volatile("cp.async.cg.shared.global [%0], [%1], 16, %2;" \
                 :: "r"(dst), "l"(src), "r"(nbytes))
#define CP_COMMIT() asm volatile("cp.async.commit_group;" ::: "memory")
#define CP_WAIT0()  asm volatile("cp.async.wait_group 0;"  ::: "memory")

#define LDMX4(r, addr) \
    asm volatile("ldmatrix.sync.aligned.m8n8.x4.shared.b16 {%0,%1,%2,%3}, [%4];" \
                 : "=r"((r)[0]), "=r"((r)[1]), "=r"((r)[2]), "=r"((r)[3]) : "r"(addr))

#define MMA16816(d, a, b0, b1) \
    asm volatile("mma.sync.aligned.m16n8k16.row.col.f32.bf16.bf16.f32 " \
                 "{%0,%1,%2,%3}, {%4,%5,%6,%7}, {%8,%9}, {%0,%1,%2,%3};" \
                 : "+f"((d)[0]), "+f"((d)[1]), "+f"((d)[2]), "+f"((d)[3]) \
                 : "r"((a)[0]), "r"((a)[1]), "r"((a)[2]), "r"((a)[3]), \
                   "r"(b0), "r"(b1))

// ---------------------------------------------------------------------------
// Fused fp32 -> bf16 hi/lo split; 4 consecutive float4s per thread.
// ---------------------------------------------------------------------------
static constexpr int X4  = TOK * D / 4;
static constexpr int WQ4 = H3 * D / 4;
static constexpr int WG4 = D * D / 4;
static constexpr int WO4 = D * D / 4;
static constexpr int TOT4 = X4 + WQ4 + WG4 + WO4;

__global__ __launch_bounds__(256) void split_all_kernel(
    const float4* __restrict__ x, const float4* __restrict__ wq,
    const float4* __restrict__ wg, const float4* __restrict__ wo,
    uint2* __restrict__ xh, uint2* __restrict__ xl,
    uint2* __restrict__ wfh, uint2* __restrict__ wfl,
    uint2* __restrict__ woh, uint2* __restrict__ wol)
{
    int i0 = (blockIdx.x * 256 + threadIdx.x) * 4;
    if (i0 >= TOT4) return;

    const float4* src; uint2 *dh, *dl; int j;
    if (i0 < X4)                 { src = x;  dh = xh;  dl = xl;  j = i0; }
    else if (i0 < X4 + WQ4)      { src = wq; dh = wfh; dl = wfl; j = i0 - X4; }
    else if (i0 < X4 + WQ4 + WG4){ src = wg; dh = wfh + WQ4; dl = wfl + WQ4; j = i0 - X4 - WQ4; }
    else                         { src = wo; dh = woh; dl = wol; j = i0 - X4 - WQ4 - WG4; }

    float4 a4[4];
#pragma unroll
    for (int t = 0; t < 4; t++) a4[t] = src[j + t];

#pragma unroll
    for (int t = 0; t < 4; t++) {
        float av[4] = {a4[t].x, a4[t].y, a4[t].z, a4[t].w};
        uint32_t hh[4], ll[4];
#pragma unroll
        for (int k = 0; k < 4; k++) {
            __nv_bfloat16 h = __float2bfloat16(av[k]);
            float r = av[k] - __bfloat162float(h);
            __nv_bfloat16 l = __float2bfloat16(r);
            hh[k] = (uint32_t)__bfloat16_as_ushort(h);
            ll[k] = (uint32_t)__bfloat16_as_ushort(l);
        }
        uint2 hv, lv;
        hv.x = hh[0] | (hh[1] << 16); hv.y = hh[2] | (hh[3] << 16);
        lv.x = ll[0] | (ll[1] << 16); lv.y = ll[2] | (ll[3] << 16);
        dh[j + t] = hv; dl[j + t] = lv;
    }
}

// ---------------------------------------------------------------------------
// HMMA GEMM (exact R13 winner): CTA 64x128, 8 warps (warp tile 32x32),
// K-chunk 64, 2-stage cp.async, single __syncthreads per chunk, 2 CTAs/SM.
// m-fastest rasterization (B-tile L2 sharing), hoisted bias.
// Dual epilogue (CTA-uniform): n<NSPLIT -> C0+bias0 else sigmoid -> C1.
// ---------------------------------------------------------------------------
__global__ __launch_bounds__(256, 2) void hmma_gemm(
    const __nv_bfloat16* __restrict__ Ah, const __nv_bfloat16* __restrict__ Al,
    const __nv_bfloat16* __restrict__ Bh, const __nv_bfloat16* __restrict__ Bl,
    const float* __restrict__ bias0, const float* __restrict__ bias1,
    float* __restrict__ C0, float* __restrict__ C1,
    int N, int K, int NSPLIT)
{
    constexpr uint32_t A_SZ  = 64 * 128;
    constexpr uint32_t B_SZ  = 128 * 128;
    constexpr uint32_t OFF_AL = A_SZ;
    constexpr uint32_t OFF_BH = 2 * A_SZ;
    constexpr uint32_t OFF_BL = 2 * A_SZ + B_SZ;
    constexpr uint32_t STG    = 2 * A_SZ + 2 * B_SZ;  // 48KB

    extern __shared__ char smraw[];
    uint32_t sb = (smem_u32(smraw) + 127u) & ~127u;

    const int tid  = threadIdx.x;
    const int lane = tid & 31;
    const int wid  = tid >> 5;
    const int wm   = wid & 1;
    const int wn   = wid >> 1;
    const int m0 = blockIdx.x * 64;    // m fastest -> B-tile L2 sharing
    const int n0 = blockIdx.y * 128;

    const int nchunk = K >> 6;

    float acc[2][4][4];
#pragma unroll
    for (int i = 0; i < 2; i++)
#pragma unroll
        for (int j = 0; j < 4; j++)
#pragma unroll
            for (int q = 0; q < 4; q++) acc[i][j][q] = 0.f;

    const int a_r  = wm * 32 + ((lane >> 3) & 1) * 8 + (lane & 7);
    const int a_kc = (lane >> 4);
    const int b_r  = wn * 32 + ((lane >> 4) & 1) * 8 + (lane & 7);
    const int b_kc = ((lane >> 3) & 1);

    auto load_tile = [&](int i) {
        const int kb = i * 64;
        const uint32_t base = sb + (uint32_t)(i & 1) * STG;
#pragma unroll
        for (int t = 0; t < 2; t++) {
            int u = tid + t * 256;
            int row = u >> 3, c = u & 7;
            uint32_t sw = (uint32_t)row * 128u + (uint32_t)((c ^ (row & 7)) * 16);
            const size_t g = (size_t)(m0 + row) * K + kb + c * 8;
            CP_ASYNC16(base + sw,          (const void*)(Ah + g));
            CP_ASYNC16(base + OFF_AL + sw, (const void*)(Al + g));
        }
#pragma unroll
        for (int t = 0; t < 4; t++) {
            int u = tid + t * 256;
            int row = u >> 3, c = u & 7;
            uint32_t sw = (uint32_t)row * 128u + (uint32_t)((c ^ (row & 7)) * 16);
            const size_t g = (size_t)(n0 + row) * K + kb + c * 8;
            CP_ASYNC16(base + OFF_BH + sw, (const void*)(Bh + g));
            CP_ASYNC16(base + OFF_BL + sw, (const void*)(Bl + g));
        }
    };

    load_tile(0);
    CP_COMMIT();

    for (int i = 0; i < nchunk; i++) {
        CP_WAIT0();
        __syncthreads();

        if (i + 1 < nchunk) load_tile(i + 1);
        CP_COMMIT();

        const uint32_t base = sb + (uint32_t)(i & 1) * STG;

#pragma unroll
        for (int ks = 0; ks < 4; ks++) {
            uint32_t afh[2][4], afl[2][4], bfh[2][4], bfl[2][4];
#pragma unroll
            for (int mi = 0; mi < 2; mi++) {
                int r = a_r + mi * 16;
                uint32_t sw = (uint32_t)(((ks * 2 + a_kc) ^ (r & 7)) * 16);
                LDMX4(afh[mi], base + (uint32_t)r * 128u + sw);
                LDMX4(afl[mi], base + OFF_AL + (uint32_t)r * 128u + sw);
            }
#pragma unroll
            for (int ng = 0; ng < 2; ng++) {
                int r = b_r + ng * 16;
                uint32_t sw = (uint32_t)(((ks * 2 + b_kc) ^ (r & 7)) * 16);
                LDMX4(bfh[ng], base + OFF_BH + (uint32_t)r * 128u + sw);
                LDMX4(bfl[ng], base + OFF_BL + (uint32_t)r * 128u + sw);
            }

            // pass 1: Ah * Bh
#pragma unroll
            for (int mi = 0; mi < 2; mi++)
#pragma unroll
                for (int ni = 0; ni < 4; ni++)
                    MMA16816(acc[mi][ni], afh[mi],
                             bfh[ni >> 1][(ni & 1) * 2], bfh[ni >> 1][(ni & 1) * 2 + 1]);
            // pass 2: Al * Bh
#pragma unroll
            for (int mi = 0; mi < 2; mi++)
#pragma unroll
                for (int ni = 0; ni < 4; ni++)
                    MMA16816(acc[mi][ni], afl[mi],
                             bfh[ni >> 1][(ni & 1) * 2], bfh[ni >> 1][(ni & 1) * 2 + 1]);
            // pass 3: Ah * Bl
#pragma unroll
            for (int mi = 0; mi < 2; mi++)
#pragma unroll
                for (int ni = 0; ni < 4; ni++)
                    MMA16816(acc[mi][ni], afh[mi],
                             bfl[ni >> 1][(ni & 1) * 2], bfl[ni >> 1][(ni & 1) * 2 + 1]);
        }
    }

    const bool   gate_tile = (n0 >= NSPLIT);
    float*       Cb    = gate_tile ? C1 : C0;
    const float* bb    = gate_tile ? bias1 : bias0;
    const int    ncols = gate_tile ? (N - NSPLIT) : NSPLIT;
    const int    nb0   = n0 - (gate_tile ? NSPLIT : 0);

    const int mrow = lane >> 2;
    const int ncol = (lane & 3) * 2;

    float2 bias_r[4];
#pragma unroll
    for (int ni = 0; ni < 4; ni++) {
        const int n = nb0 + wn * 32 + ni * 8 + ncol;
        bias_r[ni] = *(const float2*)(bb + n);
    }

#pragma unroll
    for (int mi = 0; mi < 2; mi++) {
#pragma unroll
        for (int half = 0; half < 2; half++) {
            const int m = m0 + wm * 32 + mi * 16 + mrow + half * 8;
            float* crow = Cb + (size_t)m * ncols;
#pragma unroll
            for (int ni = 0; ni < 4; ni++) {
                const int n = nb0 + wn * 32 + ni * 8 + ncol;
                float v0 = acc[mi][ni][half * 2 + 0] + bias_r[ni].x;
                float v1 = acc[mi][ni][half * 2 + 1] + bias_r[ni].y;
                if (gate_tile) {
                    v0 = 1.f / (1.f + __expf(-v0));
                    v1 = 1.f / (1.f + __expf(-v1));
                }
                float2 o = {v0, v1};
                *(float2*)(crow + n) = o;
            }
        }
    }
}

// ---------------------------------------------------------------------------
// Attention (R13 winner + cp.async staging): CTA = 16 tokens x 1 head,
// 16 warps (512 thr), one warp per (token, head); dense K/V rows [t0-32,
// t0+16) staged via cp.async (zero-fill halo); butterfly multi-reduce for
// dense AND sparse score sets.
// ---------------------------------------------------------------------------
__global__ __launch_bounds__(512) void attn_kernel(
    const float* __restrict__ qkv, const float* __restrict__ gate,
    const float* __restrict__ pos_bias,
    __nv_bfloat16* __restrict__ a2h, __nv_bfloat16* __restrict__ a2l)
{
    __shared__ float sK[48 * 64];
    __shared__ float sV[48 * 64];

    const int t0   = blockIdx.x * 16;
    const int h    = blockIdx.y;
    const int tid  = threadIdx.x;
    const int lane = tid & 31;
    const int w    = tid >> 5;

    // stage K/V rows t0-32 .. t0+15 with cp.async; out-of-range rows zero-fill
    {
        const uint32_t skb = smem_u32(sK);
        const uint32_t svb = smem_u32(sV);
#pragma unroll
        for (int t = 0; t < 2; t++) {                 // 48*16=768 chunks, 512 thr
            int idx = tid + t * 512;
            if (idx < 48 * 16) {
                const int row = idx >> 4, c4 = idx & 15;
                const int gt = t0 - 32 + row;
                const int valid = (gt >= 0) ? 16 : 0;
                const int gts = (gt >= 0) ? gt : 0;   // keep address in-bounds
                const float* srcK = qkv + (size_t)gts * H3 + D + h * 64 + c4 * 4;
                const uint32_t off = (uint32_t)(row * 64 + c4 * 4) * 4u;
                CP_ASYNC16_Z(skb + off, (const void*)srcK,       valid);
                CP_ASYNC16_Z(svb + off, (const void*)(srcK + D), valid);
            }
        }
    }
    CP_COMMIT();
    CP_WAIT0();
    __syncthreads();

    const int n    = t0 + w;
    const int base = w + 32;
    const float2 q2 = *(const float2*)(qkv + (size_t)n * H3 + h * 64 + lane * 2);
    const float NEG = -1e30f;
    const int offs_sp[12] = {32,48,64,96,128,192,256,384,512,768,1024,1536};

    // ---- dense offsets 0..31 from smem, butterfly multi-reduce ----
    float r[32];
#pragma unroll
    for (int o = 0; o < 32; o++) {
        const float2 k2 = *(const float2*)(sK + (base - o) * 64 + lane * 2);
        r[o] = q2.x * k2.x + q2.y * k2.y;
    }
#pragma unroll
    for (int m = 16, cnt = 32; m >= 1; m >>= 1, cnt >>= 1) {
        const int half = cnt >> 1;
        const bool hi = (lane & m) != 0;
#pragma unroll
        for (int i = 0; i < 16; i++) {
            if (i < half) {
                float a = r[i], b = r[i + half];
                float sel = hi ? a : b;
                float got = __shfl_xor_sync(0xffffffffu, sel, m);
                r[i] = hi ? (b + got) : (a + got);
            }
        }
    }
    float s0 = (n - lane >= 0) ? (r[0] * 0.125f + pos_bias[lane * NH + h]) : NEG;

    // ---- sparse offsets via a second butterfly (12 values, zero-padded) ----
    float q[32];
#pragma unroll
    for (int j = 0; j < 12; j++) {
        const int off = offs_sp[j];
        const int src = n - off;
        float p = 0.f;
        if (src >= 0) {
            float2 k2;
            if (off == 32) k2 = *(const float2*)(sK + (base - 32) * 64 + lane * 2);
            else           k2 = *(const float2*)(qkv + (size_t)src * H3 + D + h * 64 + lane * 2);
            p = q2.x * k2.x + q2.y * k2.y;
        }
        q[j] = p;
    }
#pragma unroll
    for (int j = 12; j < 32; j++) q[j] = 0.f;
#pragma unroll
    for (int m = 16, cnt = 32; m >= 1; m >>= 1, cnt >>= 1) {
        const int half = cnt >> 1;
        const bool hi = (lane & m) != 0;
#pragma unroll
        for (int i = 0; i < 16; i++) {
            if (i < half) {
                float a = q[i], b = q[i + half];
                float sel = hi ? a : b;
                float got = __shfl_xor_sync(0xffffffffu, sel, m);
                q[i] = hi ? (b + got) : (a + got);
            }
        }
    }
    float s1 = NEG;
    if (lane < 12) {
        const int off_l = c_offs[32 + lane];
        if (n - off_l >= 0)
            s1 = q[0] * 0.125f + pos_bias[(32 + lane) * NH + h];
    }

    // ---- softmax over 44 distributed scores ----
    float m = fmaxf(s0, s1);
    m = fmaxf(m, __shfl_xor_sync(0xffffffffu, m, 16));
    m = fmaxf(m, __shfl_xor_sync(0xffffffffu, m, 8));
    m = fmaxf(m, __shfl_xor_sync(0xffffffffu, m, 4));
    m = fmaxf(m, __shfl_xor_sync(0xffffffffu, m, 2));
    m = fmaxf(m, __shfl_xor_sync(0xffffffffu, m, 1));

    float e0 = (s0 > NEG) ? __expf(s0 - m) : 0.f;
    float e1 = (s1 > NEG) ? __expf(s1 - m) : 0.f;

    float sum = e0 + e1;
    sum += __shfl_xor_sync(0xffffffffu, sum, 16);
    sum += __shfl_xor_sync(0xffffffffu, sum, 8);
    sum += __shfl_xor_sync(0xffffffffu, sum, 4);
    sum += __shfl_xor_sync(0xffffffffu, sum, 2);
    sum += __shfl_xor_sync(0xffffffffu, sum, 1);
    const float inv = 1.f / sum;

    // ---- weighted V sum: dense (and off=32) from smem, rest from L2 ----
    float acc0 = 0.f, acc1 = 0.f;
#pragma unroll
    for (int o = 0; o < 32; o++) {
        float al = __shfl_sync(0xffffffffu, e0, o);
        const float2 v2 = *(const float2*)(sV + (base - o) * 64 + lane * 2);
        acc0 = fmaf(al, v2.x, acc0);
        acc1 = fmaf(al, v2.y, acc1);
    }
#pragma unroll
    for (int j = 0; j < 12; j++) {
        const int off = offs_sp[j];
        const int src = n - off;
        if (src >= 0) {
            float al = __shfl_sync(0xffffffffu, e1, j);
            float2 v2;
            if (off == 32) v2 = *(const float2*)(sV + (base - 32) * 64 + lane * 2);
            else           v2 = *(const float2*)(qkv + (size_t)src * H3 + 2 * D + h * 64 + lane * 2);
            acc0 = fmaf(al, v2.x, acc0);
            acc1 = fmaf(al, v2.y, acc1);
        }
    }
    acc0 *= inv;
    acc1 *= inv;

    const int oi2 = n * D + h * 64 + lane * 2;
    const float2 g2 = *(const float2*)(gate + oi2);
    float v0 = acc0 * g2.x;
    float v1 = acc1 * g2.y;

    __nv_bfloat16 h0 = __float2bfloat16(v0);
    __nv_bfloat16 h1 = __float2bfloat16(v1);
    a2h[oi2]     = h0;
    a2h[oi2 + 1] = h1;
    a2l[oi2]     = __float2bfloat16(v0 - __bfloat162float(h0));
    a2l[oi2 + 1] = __float2bfloat16(v1 - __bfloat162float(h1));
}

// ---------------------------------------------------------------------------
// kernel_launch
// ---------------------------------------------------------------------------
extern "C" void kernel_launch(void* const* d_in, const int* in_sizes, int n_in,
                              void* d_out, int out_size)
{
    const float* x        = (const float*)d_in[0];
    const float* Wqkv     = (const float*)d_in[1];
    const float* bqkv     = (const float*)d_in[2];
    const float* Wout     = (const float*)d_in[3];
    const float* bout     = (const float*)d_in[4];
    const float* Wgate    = (const float*)d_in[5];
    const float* bgate    = (const float*)d_in[6];
    const float* pos_bias = (const float*)d_in[7];
    float* out = (float*)d_out;

    float *qkv, *gate;
    __nv_bfloat16 *xh, *xl, *wfh, *wfl, *woh, *wol, *a2h, *a2l;
    cudaGetSymbolAddress((void**)&qkv,  g_qkv);
    cudaGetSymbolAddress((void**)&gate, g_gate);
    cudaGetSymbolAddress((void**)&xh,  g_xh);  cudaGetSymbolAddress((void**)&xl,  g_xl);
    cudaGetSymbolAddress((void**)&wfh, g_wfh); cudaGetSymbolAddress((void**)&wfl, g_wfl);
    cudaGetSymbolAddress((void**)&woh, g_woh); cudaGetSymbolAddress((void**)&wol, g_wol);
    cudaGetSymbolAddress((void**)&a2h, g_a2h); cudaGetSymbolAddress((void**)&a2l, g_a2l);

    const int SMEM_GEMM = 128 + 2 * (2 * 64 * 128 + 2 * 128 * 128);  // 128 + 98304
    cudaFuncSetAttribute(hmma_gemm, cudaFuncAttributeMaxDynamicSharedMemorySize, SMEM_GEMM);

    // 1) all fp32 -> bf16 hi/lo splits (4 float4s per thread)
    split_all_kernel<<<(TOT4 / 4 + 255) / 256, 256>>>(
        (const float4*)x, (const float4*)Wqkv, (const float4*)Wgate, (const float4*)Wout,
        (uint2*)xh, (uint2*)xl, (uint2*)wfh, (uint2*)wfl, (uint2*)woh, (uint2*)wol);

    // 2) fused qkv+gate GEMM: [2048, 4096] = x @ [Wqkv; Wgate]^T   (1024 CTAs)
    hmma_gemm<<<dim3(TOK / 64, (H3 + D) / 128), 256, SMEM_GEMM>>>(
        xh, xl, wfh, wfl, bqkv, bgate, qkv, gate, H3 + D, D, H3);

    // 3) attention + gate -> split a2   (128 token groups x 16 heads)
    attn_kernel<<<dim3(TOK / 16, NH), 512>>>(qkv, gate, pos_bias, a2h, a2l);

    // 4) out = a2 @ Wout^T + bout   (256 CTAs)
    hmma_gemm<<<dim3(TOK / 64, D / 128), 256, SMEM_GEMM>>>(
        a2h, a2l, woh, wol, bout, bout, out, nullptr, D, D, D);
}

// round 17
// speedup vs baseline: 1.0477x; 1.0110x over previous
#include <cuda_runtime.h>
#include <cuda_bf16.h>
#include <cstdint>

// ---------------------------------------------------------------------------
// Problem constants
// ---------------------------------------------------------------------------
static constexpr int TOK = 2048;
static constexpr int D   = 1024;
static constexpr int H3  = 3072;
static constexpr int NH  = 16;
static constexpr int NOFF = 44;

__device__ __constant__ int c_offs[NOFF] = {
    0,1,2,3,4,5,6,7,8,9,10,11,12,13,14,15,16,17,18,19,20,21,22,23,24,
    25,26,27,28,29,30,31,32,48,64,96,128,192,256,384,512,768,1024,1536};

// ---------------------------------------------------------------------------
// Scratch (allocation-free)
// ---------------------------------------------------------------------------
__device__ float g_qkv [TOK * H3];
__device__ float g_gate[TOK * D];
__device__ __nv_bfloat16 g_xh [TOK * D],      g_xl [TOK * D];
__device__ __nv_bfloat16 g_wfh[(H3 + D) * D], g_wfl[(H3 + D) * D];  // [Wqkv; Wgate]
__device__ __nv_bfloat16 g_woh[D * D],        g_wol[D * D];
__device__ __nv_bfloat16 g_a2h[TOK * D],      g_a2l[TOK * D];

// ---------------------------------------------------------------------------
// PTX helpers (portable sm_80+ PTX only)
// ---------------------------------------------------------------------------
__device__ __forceinline__ uint32_t smem_u32(const void* p) {
    uint32_t a;
    asm("{ .reg .u64 t; cvta.to.shared.u64 t, %1; cvt.u32.u64 %0, t; }"
        : "=r"(a) : "l"(p));
    return a;
}

#define CP_ASYNC16(dst, src) \
    asm volatile("cp.async.cg.shared.global [%0], [%1], 16;" :: "r"(dst), "l"(src))
#define CP_ASYNC16_Z(dst, src, nbytes) \
    asm volatile("cp.async.cg.shared.global [%0], [%1], 16, %2;" \
                 :: "r"(dst), "l"(src), "r"(nbytes))
#define CP_COMMIT() asm volatile("cp.async.commit_group;" ::: "memory")
#define CP_WAIT0()  asm volatile("cp.async.wait_group 0;"  ::: "memory")

#define LDMX4(r, addr) \
    asm volatile("ldmatrix.sync.aligned.m8n8.x4.shared.b16 {%0,%1,%2,%3}, [%4];" \
                 : "=r"((r)[0]), "=r"((r)[1]), "=r"((r)[2]), "=r"((r)[3]) : "r"(addr))

#define MMA16816(d, a, b0, b1) \
    asm volatile("mma.sync.aligned.m16n8k16.row.col.f32.bf16.bf16.f32 " \
                 "{%0,%1,%2,%3}, {%4,%5,%6,%7}, {%8,%9}, {%0,%1,%2,%3};" \
                 : "+f"((d)[0]), "+f"((d)[1]), "+f"((d)[2]), "+f"((d)[3]) \
                 : "r"((a)[0]), "r"((a)[1]), "r"((a)[2]), "r"((a)[3]), \
                   "r"(b0), "r"(b1))

// ---------------------------------------------------------------------------
// Fused fp32 -> bf16 hi/lo split; 4 consecutive float4s per thread.
// ---------------------------------------------------------------------------
static constexpr int X4  = TOK * D / 4;
static constexpr int WQ4 = H3 * D / 4;
static constexpr int WG4 = D * D / 4;
static constexpr int WO4 = D * D / 4;
static constexpr int TOT4 = X4 + WQ4 + WG4 + WO4;

__global__ __launch_bounds__(256) void split_all_kernel(
    const float4* __restrict__ x, const float4* __restrict__ wq,
    const float4* __restrict__ wg, const float4* __restrict__ wo,
    uint2* __restrict__ xh, uint2* __restrict__ xl,
    uint2* __restrict__ wfh, uint2* __restrict__ wfl,
    uint2* __restrict__ woh, uint2* __restrict__ wol)
{
    int i0 = (blockIdx.x * 256 + threadIdx.x) * 4;
    if (i0 >= TOT4) return;

    const float4* src; uint2 *dh, *dl; int j;
    if (i0 < X4)                 { src = x;  dh = xh;  dl = xl;  j = i0; }
    else if (i0 < X4 + WQ4)      { src = wq; dh = wfh; dl = wfl; j = i0 - X4; }
    else if (i0 < X4 + WQ4 + WG4){ src = wg; dh = wfh + WQ4; dl = wfl + WQ4; j = i0 - X4 - WQ4; }
    else                         { src = wo; dh = woh; dl = wol; j = i0 - X4 - WQ4 - WG4; }

    float4 a4[4];
#pragma unroll
    for (int t = 0; t < 4; t++) a4[t] = src[j + t];

#pragma unroll
    for (int t = 0; t < 4; t++) {
        float av[4] = {a4[t].x, a4[t].y, a4[t].z, a4[t].w};
        uint32_t hh[4], ll[4];
#pragma unroll
        for (int k = 0; k < 4; k++) {
            __nv_bfloat16 h = __float2bfloat16(av[k]);
            float r = av[k] - __bfloat162float(h);
            __nv_bfloat16 l = __float2bfloat16(r);
            hh[k] = (uint32_t)__bfloat16_as_ushort(h);
            ll[k] = (uint32_t)__bfloat16_as_ushort(l);
        }
        uint2 hv, lv;
        hv.x = hh[0] | (hh[1] << 16); hv.y = hh[2] | (hh[3] << 16);
        lv.x = ll[0] | (ll[1] << 16); lv.y = ll[2] | (ll[3] << 16);
        dh[j + t] = hv; dl[j + t] = lv;
    }
}

// ---------------------------------------------------------------------------
// HMMA GEMM (frozen R13 winner): CTA 64x128, 8 warps (warp tile 32x32),
// K-chunk 64, 2-stage cp.async, single __syncthreads per chunk, 2 CTAs/SM.
// m-fastest rasterization (B-tile L2 sharing), hoisted bias.
// Dual epilogue (CTA-uniform): n<NSPLIT -> C0+bias0 else sigmoid -> C1.
// ---------------------------------------------------------------------------
__global__ __launch_bounds__(256, 2) void hmma_gemm(
    const __nv_bfloat16* __restrict__ Ah, const __nv_bfloat16* __restrict__ Al,
    const __nv_bfloat16* __restrict__ Bh, const __nv_bfloat16* __restrict__ Bl,
    const float* __restrict__ bias0, const float* __restrict__ bias1,
    float* __restrict__ C0, float* __restrict__ C1,
    int N, int K, int NSPLIT)
{
    constexpr uint32_t A_SZ  = 64 * 128;
    constexpr uint32_t B_SZ  = 128 * 128;
    constexpr uint32_t OFF_AL = A_SZ;
    constexpr uint32_t OFF_BH = 2 * A_SZ;
    constexpr uint32_t OFF_BL = 2 * A_SZ + B_SZ;
    constexpr uint32_t STG    = 2 * A_SZ + 2 * B_SZ;  // 48KB

    extern __shared__ char smraw[];
    uint32_t sb = (smem_u32(smraw) + 127u) & ~127u;

    const int tid  = threadIdx.x;
    const int lane = tid & 31;
    const int wid  = tid >> 5;
    const int wm   = wid & 1;
    const int wn   = wid >> 1;
    const int m0 = blockIdx.x * 64;    // m fastest -> B-tile L2 sharing
    const int n0 = blockIdx.y * 128;

    const int nchunk = K >> 6;

    float acc[2][4][4];
#pragma unroll
    for (int i = 0; i < 2; i++)
#pragma unroll
        for (int j = 0; j < 4; j++)
#pragma unroll
            for (int q = 0; q < 4; q++) acc[i][j][q] = 0.f;

    const int a_r  = wm * 32 + ((lane >> 3) & 1) * 8 + (lane & 7);
    const int a_kc = (lane >> 4);
    const int b_r  = wn * 32 + ((lane >> 4) & 1) * 8 + (lane & 7);
    const int b_kc = ((lane >> 3) & 1);

    auto load_tile = [&](int i) {
        const int kb = i * 64;
        const uint32_t base = sb + (uint32_t)(i & 1) * STG;
#pragma unroll
        for (int t = 0; t < 2; t++) {
            int u = tid + t * 256;
            int row = u >> 3, c = u & 7;
            uint32_t sw = (uint32_t)row * 128u + (uint32_t)((c ^ (row & 7)) * 16);
            const size_t g = (size_t)(m0 + row) * K + kb + c * 8;
            CP_ASYNC16(base + sw,          (const void*)(Ah + g));
            CP_ASYNC16(base + OFF_AL + sw, (const void*)(Al + g));
        }
#pragma unroll
        for (int t = 0; t < 4; t++) {
            int u = tid + t * 256;
            int row = u >> 3, c = u & 7;
            uint32_t sw = (uint32_t)row * 128u + (uint32_t)((c ^ (row & 7)) * 16);
            const size_t g = (size_t)(n0 + row) * K + kb + c * 8;
            CP_ASYNC16(base + OFF_BH + sw, (const void*)(Bh + g));
            CP_ASYNC16(base + OFF_BL + sw, (const void*)(Bl + g));
        }
    };

    load_tile(0);
    CP_COMMIT();

    for (int i = 0; i < nchunk; i++) {
        CP_WAIT0();
        __syncthreads();

        if (i + 1 < nchunk) load_tile(i + 1);
        CP_COMMIT();

        const uint32_t base = sb + (uint32_t)(i & 1) * STG;

#pragma unroll
        for (int ks = 0; ks < 4; ks++) {
            uint32_t afh[2][4], afl[2][4], bfh[2][4], bfl[2][4];
#pragma unroll
            for (int mi = 0; mi < 2; mi++) {
                int r = a_r + mi * 16;
                uint32_t sw = (uint32_t)(((ks * 2 + a_kc) ^ (r & 7)) * 16);
                LDMX4(afh[mi], base + (uint32_t)r * 128u + sw);
                LDMX4(afl[mi], base + OFF_AL + (uint32_t)r * 128u + sw);
            }
#pragma unroll
            for (int ng = 0; ng < 2; ng++) {
                int r = b_r + ng * 16;
                uint32_t sw = (uint32_t)(((ks * 2 + b_kc) ^ (r & 7)) * 16);
                LDMX4(bfh[ng], base + OFF_BH + (uint32_t)r * 128u + sw);
                LDMX4(bfl[ng], base + OFF_BL + (uint32_t)r * 128u + sw);
            }

            // pass 1: Ah * Bh
#pragma unroll
            for (int mi = 0; mi < 2; mi++)
#pragma unroll
                for (int ni = 0; ni < 4; ni++)
                    MMA16816(acc[mi][ni], afh[mi],
                             bfh[ni >> 1][(ni & 1) * 2], bfh[ni >> 1][(ni & 1) * 2 + 1]);
            // pass 2: Al * Bh
#pragma unroll
            for (int mi = 0; mi < 2; mi++)
#pragma unroll
                for (int ni = 0; ni < 4; ni++)
                    MMA16816(acc[mi][ni], afl[mi],
                             bfh[ni >> 1][(ni & 1) * 2], bfh[ni >> 1][(ni & 1) * 2 + 1]);
            // pass 3: Ah * Bl
#pragma unroll
            for (int mi = 0; mi < 2; mi++)
#pragma unroll
                for (int ni = 0; ni < 4; ni++)
                    MMA16816(acc[mi][ni], afh[mi],
                             bfl[ni >> 1][(ni & 1) * 2], bfl[ni >> 1][(ni & 1) * 2 + 1]);
        }
    }

    const bool   gate_tile = (n0 >= NSPLIT);
    float*       Cb    = gate_tile ? C1 : C0;
    const float* bb    = gate_tile ? bias1 : bias0;
    const int    ncols = gate_tile ? (N - NSPLIT) : NSPLIT;
    const int    nb0   = n0 - (gate_tile ? NSPLIT : 0);

    const int mrow = lane >> 2;
    const int ncol = (lane & 3) * 2;

    float2 bias_r[4];
#pragma unroll
    for (int ni = 0; ni < 4; ni++) {
        const int n = nb0 + wn * 32 + ni * 8 + ncol;
        bias_r[ni] = *(const float2*)(bb + n);
    }

#pragma unroll
    for (int mi = 0; mi < 2; mi++) {
#pragma unroll
        for (int half = 0; half < 2; half++) {
            const int m = m0 + wm * 32 + mi * 16 + mrow + half * 8;
            float* crow = Cb + (size_t)m * ncols;
#pragma unroll
            for (int ni = 0; ni < 4; ni++) {
                const int n = nb0 + wn * 32 + ni * 8 + ncol;
                float v0 = acc[mi][ni][half * 2 + 0] + bias_r[ni].x;
                float v1 = acc[mi][ni][half * 2 + 1] + bias_r[ni].y;
                if (gate_tile) {
                    v0 = 1.f / (1.f + __expf(-v0));
                    v1 = 1.f / (1.f + __expf(-v1));
                }
                float2 o = {v0, v1};
                *(float2*)(crow + n) = o;
            }
        }
    }
}

// ---------------------------------------------------------------------------
// Attention: CTA = 16 tokens x 1 head, 16 warps (512 thr), one warp per
// (token, head). K/V rows [t0-64, t0+16) (80 rows, 40KB) staged via cp.async
// (zero-fill halo) — covers offsets 0..64; only 9 sparse offsets hit L2.
// Butterfly multi-reduce for dense AND sparse score sets.
// ---------------------------------------------------------------------------
__global__ __launch_bounds__(512) void attn_kernel(
    const float* __restrict__ qkv, const float* __restrict__ gate,
    const float* __restrict__ pos_bias,
    __nv_bfloat16* __restrict__ a2h, __nv_bfloat16* __restrict__ a2l)
{
    __shared__ float sK[80 * 64];
    __shared__ float sV[80 * 64];

    const int t0   = blockIdx.x * 16;
    const int h    = blockIdx.y;
    const int tid  = threadIdx.x;
    const int lane = tid & 31;
    const int w    = tid >> 5;

    // stage K/V rows t0-64 .. t0+15 with cp.async; out-of-range rows zero-fill
    {
        const uint32_t skb = smem_u32(sK);
        const uint32_t svb = smem_u32(sV);
#pragma unroll
        for (int t = 0; t < 3; t++) {                 // 80*16=1280 chunks, 512 thr
            int idx = tid + t * 512;
            if (idx < 80 * 16) {
                const int row = idx >> 4, c4 = idx & 15;
                const int gt = t0 - 64 + row;
                const int valid = (gt >= 0) ? 16 : 0;
                const int gts = (gt >= 0) ? gt : 0;   // keep address in-bounds
                const float* srcK = qkv + (size_t)gts * H3 + D + h * 64 + c4 * 4;
                const uint32_t off = (uint32_t)(row * 64 + c4 * 4) * 4u;
                CP_ASYNC16_Z(skb + off, (const void*)srcK,       valid);
                CP_ASYNC16_Z(svb + off, (const void*)(srcK + D), valid);
            }
        }
    }
    CP_COMMIT();
    CP_WAIT0();
    __syncthreads();

    const int n    = t0 + w;
    const int base = w + 64;                      // smem row for offset 0
    const float2 q2 = *(const float2*)(qkv + (size_t)n * H3 + h * 64 + lane * 2);
    const float NEG = -1e30f;
    const int offs_sp[12] = {32,48,64,96,128,192,256,384,512,768,1024,1536};

    // ---- dense offsets 0..31 from smem, butterfly multi-reduce ----
    float r[32];
#pragma unroll
    for (int o = 0; o < 32; o++) {
        const float2 k2 = *(const float2*)(sK + (base - o) * 64 + lane * 2);
        r[o] = q2.x * k2.x + q2.y * k2.y;
    }
#pragma unroll
    for (int m = 16, cnt = 32; m >= 1; m >>= 1, cnt >>= 1) {
        const int half = cnt >> 1;
        const bool hi = (lane & m) != 0;
#pragma unroll
        for (int i = 0; i < 16; i++) {
            if (i < half) {
                float a = r[i], b = r[i + half];
                float sel = hi ? a : b;
                float got = __shfl_xor_sync(0xffffffffu, sel, m);
                r[i] = hi ? (b + got) : (a + got);
            }
        }
    }
    float s0 = (n - lane >= 0) ? (r[0] * 0.125f + pos_bias[lane * NH + h]) : NEG;

    // ---- sparse offsets via a second butterfly; offs <= 64 read smem ----
    float q[32];
#pragma unroll
    for (int j = 0; j < 12; j++) {
        const int off = offs_sp[j];
        const int src = n - off;
        float p = 0.f;
        if (src >= 0) {
            float2 k2;
            if (off <= 64) k2 = *(const float2*)(sK + (base - off) * 64 + lane * 2);
            else           k2 = *(const float2*)(qkv + (size_t)src * H3 + D + h * 64 + lane * 2);
            p = q2.x * k2.x + q2.y * k2.y;
        }
        q[j] = p;
    }
#pragma unroll
    for (int j = 12; j < 32; j++) q[j] = 0.f;
#pragma unroll
    for (int m = 16, cnt = 32; m >= 1; m >>= 1, cnt >>= 1) {
        const int half = cnt >> 1;
        const bool hi = (lane & m) != 0;
#pragma unroll
        for (int i = 0; i < 16; i++) {
            if (i < half) {
                float a = q[i], b = q[i + half];
                float sel = hi ? a : b;
                float got = __shfl_xor_sync(0xffffffffu, sel, m);
                q[i] = hi ? (b + got) : (a + got);
            }
        }
    }
    float s1 = NEG;
    if (lane < 12) {
        const int off_l = c_offs[32 + lane];
        if (n - off_l >= 0)
            s1 = q[0] * 0.125f + pos_bias[(32 + lane) * NH + h];
    }

    // ---- softmax over 44 distributed scores ----
    float m = fmaxf(s0, s1);
    m = fmaxf(m, __shfl_xor_sync(0xffffffffu, m, 16));
    m = fmaxf(m, __shfl_xor_sync(0xffffffffu, m, 8));
    m = fmaxf(m, __shfl_xor_sync(0xffffffffu, m, 4));
    m = fmaxf(m, __shfl_xor_sync(0xffffffffu, m, 2));
    m = fmaxf(m, __shfl_xor_sync(0xffffffffu, m, 1));

    float e0 = (s0 > NEG) ? __expf(s0 - m) : 0.f;
    float e1 = (s1 > NEG) ? __expf(s1 - m) : 0.f;

    float sum = e0 + e1;
    sum += __shfl_xor_sync(0xffffffffu, sum, 16);
    sum += __shfl_xor_sync(0xffffffffu, sum, 8);
    sum += __shfl_xor_sync(0xffffffffu, sum, 4);
    sum += __shfl_xor_sync(0xffffffffu, sum, 2);
    sum += __shfl_xor_sync(0xffffffffu, sum, 1);
    const float inv = 1.f / sum;

    // ---- weighted V sum: offsets <= 64 from smem, rest from L2 ----
    float acc0 = 0.f, acc1 = 0.f;
#pragma unroll
    for (int o = 0; o < 32; o++) {
        float al = __shfl_sync(0xffffffffu, e0, o);
        const float2 v2 = *(const float2*)(sV + (base - o) * 64 + lane * 2);
        acc0 = fmaf(al, v2.x, acc0);
        acc1 = fmaf(al, v2.y, acc1);
    }
#pragma unroll
    for (int j = 0; j < 12; j++) {
        const int off = offs_sp[j];
        const int src = n - off;
        if (src >= 0) {
            float al = __shfl_sync(0xffffffffu, e1, j);
            float2 v2;
            if (off <= 64) v2 = *(const float2*)(sV + (base - off) * 64 + lane * 2);
            else           v2 = *(const float2*)(qkv + (size_t)src * H3 + 2 * D + h * 64 + lane * 2);
            acc0 = fmaf(al, v2.x, acc0);
            acc1 = fmaf(al, v2.y, acc1);
        }
    }
    acc0 *= inv;
    acc1 *= inv;

    const int oi2 = n * D + h * 64 + lane * 2;
    const float2 g2 = *(const float2*)(gate + oi2);
    float v0 = acc0 * g2.x;
    float v1 = acc1 * g2.y;

    __nv_bfloat16 h0 = __float2bfloat16(v0);
    __nv_bfloat16 h1 = __float2bfloat16(v1);
    a2h[oi2]     = h0;
    a2h[oi2 + 1] = h1;
    a2l[oi2]     = __float2bfloat16(v0 - __bfloat162float(h0));
    a2l[oi2 + 1] = __float2bfloat16(v1 - __bfloat162float(h1));
}

// ---------------------------------------------------------------------------
// kernel_launch
// ---------------------------------------------------------------------------
extern "C" void kernel_launch(void* const* d_in, const int* in_sizes, int n_in,
                              void* d_out, int out_size)
{
    const float* x        = (const float*)d_in[0];
    const float* Wqkv     = (const float*)d_in[1];
    const float* bqkv     = (const float*)d_in[2];
    const float* Wout     = (const float*)d_in[3];
    const float* bout     = (const float*)d_in[4];
    const float* Wgate    = (const float*)d_in[5];
    const float* bgate    = (const float*)d_in[6];
    const float* pos_bias = (const float*)d_in[7];
    float* out = (float*)d_out;

    float *qkv, *gate;
    __nv_bfloat16 *xh, *xl, *wfh, *wfl, *woh, *wol, *a2h, *a2l;
    cudaGetSymbolAddress((void**)&qkv,  g_qkv);
    cudaGetSymbolAddress((void**)&gate, g_gate);
    cudaGetSymbolAddress((void**)&xh,  g_xh);  cudaGetSymbolAddress((void**)&xl,  g_xl);
    cudaGetSymbolAddress((void**)&wfh, g_wfh); cudaGetSymbolAddress((void**)&wfl, g_wfl);
    cudaGetSymbolAddress((void**)&woh, g_woh); cudaGetSymbolAddress((void**)&wol, g_wol);
    cudaGetSymbolAddress((void**)&a2h, g_a2h); cudaGetSymbolAddress((void**)&a2l, g_a2l);

    const int SMEM_GEMM = 128 + 2 * (2 * 64 * 128 + 2 * 128 * 128);  // 128 + 98304
    cudaFuncSetAttribute(hmma_gemm, cudaFuncAttributeMaxDynamicSharedMemorySize, SMEM_GEMM);

    // 1) all fp32 -> bf16 hi/lo splits (4 float4s per thread)
    split_all_kernel<<<(TOT4 / 4 + 255) / 256, 256>>>(
        (const float4*)x, (const float4*)Wqkv, (const float4*)Wgate, (const float4*)Wout,
        (uint2*)xh, (uint2*)xl, (uint2*)wfh, (uint2*)wfl, (uint2*)woh, (uint2*)wol);

    // 2) fused qkv+gate GEMM: [2048, 4096] = x @ [Wqkv; Wgate]^T   (1024 CTAs)
    hmma_gemm<<<dim3(TOK / 64, (H3 + D) / 128), 256, SMEM_GEMM>>>(
        xh, xl, wfh, wfl, bqkv, bgate, qkv, gate, H3 + D, D, H3);

    // 3) attention + gate -> split a2   (128 token groups x 16 heads)
    attn_kernel<<<dim3(TOK / 16, NH), 512>>>(qkv, gate, pos_bias, a2h, a2l);

    // 4) out = a2 @ Wout^T + bout   (256 CTAs)
    hmma_gemm<<<dim3(TOK / 64, D / 128), 256, SMEM_GEMM>>>(
        a2h, a2l, woh, wol, bout, bout, out, nullptr, D, D, D);
}